// round 17
// baseline (speedup 1.0000x reference)
#include <cuda_runtime.h>
#include <cstdint>

// Problem constants
#define DD        256
#define RAW_K     640
#define GKK       512
#define JCOLS     1024      // packed gate cols (256 features x 4 gates)
#define NODES_MAX 100000

#define BM   128
#define BN   128
#define BK   16
#define PAD  20             // [rows][k] pitch: rows*20 banks distinct mod 32 for LDSM
#define TSTRIDE (BM * PAD)  // floats per stage (10240 B)

// Static scratch — device-side references only
__device__ float g_agg[(size_t)NODES_MAX * DD];   // mean-aggregated messages
__device__ float g_Wt[2 * DD * RAW_K];            // [w][n][k], tf32-RNA rounded (W^T)
__device__ float g_Bt[JCOLS * GKK];               // [j][k], gate-interleaved, rounded
__device__ int   g_counts[NODES_MAX];

static inline int cdiv(int a, int b) { return (a + b - 1) / b; }

// ---------------- helpers ----------------
__device__ __forceinline__ uint32_t smem_u32(const void* p) {
    uint32_t a;
    asm("{ .reg .u64 t; cvta.to.shared.u64 t, %1; cvt.u32.u64 %0, t; }" : "=r"(a) : "l"(p));
    return a;
}
__device__ __forceinline__ float f2tf32f(float x) {
    uint32_t u; asm("cvt.rna.tf32.f32 %0, %1;" : "=r"(u) : "f"(x));
    return __uint_as_float(u);
}
__device__ __forceinline__ float sigmoidf_(float x) { return 1.f / (1.f + expf(-x)); }

__device__ __forceinline__ void mma_tf32(float c[4], const uint32_t a[4], const uint32_t b[2]) {
    asm volatile(
        "mma.sync.aligned.m16n8k8.row.col.f32.tf32.tf32.f32 "
        "{%0,%1,%2,%3}, {%4,%5,%6,%7}, {%8,%9}, {%0,%1,%2,%3};"
        : "+f"(c[0]), "+f"(c[1]), "+f"(c[2]), "+f"(c[3])
        : "r"(a[0]), "r"(a[1]), "r"(a[2]), "r"(a[3]), "r"(b[0]), "r"(b[1]));
}
__device__ __forceinline__ void red_add_v2(float* p, float a, float b) {
    asm volatile("red.global.add.v2.f32 [%0], {%1, %2};" :: "l"(p), "f"(a), "f"(b) : "memory");
}
__device__ __forceinline__ void cp16(uint32_t d, const void* s, uint32_t sz) {
    asm volatile("cp.async.cg.shared.global [%0], [%1], 16, %2;"
                 :: "r"(d), "l"(s), "r"(sz) : "memory");
}
#define CP_COMMIT() asm volatile("cp.async.commit_group;" ::: "memory")
#define CP_WAIT0()  asm volatile("cp.async.wait_group 0;" ::: "memory")

#define LDSM4(r0, r1, r2, r3, a) \
    asm volatile("ldmatrix.sync.aligned.m8n8.x4.shared.b16 {%0,%1,%2,%3}, [%4];" \
                 : "=r"(r0), "=r"(r1), "=r"(r2), "=r"(r3) : "r"(a))

// ---------------------------------------------------------------------------
// K0 / K1: zero + counts
// ---------------------------------------------------------------------------
__global__ void zero_kernel(int n4, int N) {
    int i = blockIdx.x * blockDim.x + threadIdx.x;
    if (i < n4) ((float4*)g_agg)[i] = make_float4(0.f, 0.f, 0.f, 0.f);
    if (i < N)  g_counts[i] = 0;
}
__global__ void count_kernel(const int* __restrict__ s_src,
                             const int* __restrict__ d_src, int M) {
    int e = blockIdx.x * blockDim.x + threadIdx.x;
    if (e < 2 * M) {
        int node = (e < M) ? s_src[e] : d_src[e - M];
        atomicAdd(&g_counts[node], 1);
    }
}

// ---------------------------------------------------------------------------
// K2a: transpose+round message weights: g_Wt[w][n][k] = W_w[k][n]
// ---------------------------------------------------------------------------
__global__ void pack_wt(const float* __restrict__ Ws, const float* __restrict__ Wd) {
    int idx = blockIdx.x * blockDim.x + threadIdx.x;
    const int n1 = DD * RAW_K;
    if (idx < n1) {
        int n = idx / RAW_K, k = idx % RAW_K;
        g_Wt[idx] = f2tf32f(Ws[k * DD + n]);
    } else if (idx < 2 * n1) {
        int i2 = idx - n1;
        int n = i2 / RAW_K, k = i2 % RAW_K;
        g_Wt[idx] = f2tf32f(Wd[k * DD + n]);
    }
}

// K2b: gate-interleaved transposed gate matrix: g_Bt[j][k], j = 4f+gate
//   gates: 0=r (W|U), 1=z (W|U), 2=xn (W|0), 3=hn (0|U)
__global__ void pack_bt(const float* __restrict__ Wg, const float* __restrict__ Ug) {
    int idx = blockIdx.x * blockDim.x + threadIdx.x;
    if (idx >= JCOLS * GKK) return;
    int j = idx / GKK, k = idx % GKK;
    int f = j >> 2, gate = j & 3;
    float v = 0.f;
    if (gate == 0)      v = (k < 256) ? Wg[k * 768 + f]       : Ug[(k - 256) * 768 + f];
    else if (gate == 1) v = (k < 256) ? Wg[k * 768 + 256 + f] : Ug[(k - 256) * 768 + 256 + f];
    else if (gate == 2) v = (k < 256) ? Wg[k * 768 + 512 + f] : 0.f;
    else                v = (k < 256) ? 0.f                   : Ug[(k - 256) * 768 + 512 + f];
    g_Bt[idx] = f2tf32f(v);
}

// ---------------------------------------------------------------------------
// K3: message GEMM (raw[M,640] @ Wt^T + b)/cnt, cp.async + ldmatrix,
//     fused mean-scatter -> g_agg
// ---------------------------------------------------------------------------
__global__ __launch_bounds__(256)
void msg_gemm_tc(const float* __restrict__ A, int wsel,
                 const float* __restrict__ bias, const int* __restrict__ src, int M)
{
    __shared__ __align__(16) float As[2][BM][PAD];
    __shared__ __align__(16) float Bs[2][BN][PAD];

    const int tid  = threadIdx.x;
    const int lane = tid & 31;
    const int warp = tid >> 5;
    const int g    = lane >> 2;
    const int tg   = lane & 3;
    const int warpM = warp & 1;        // 2 warps over M (64 rows each)
    const int warpN = warp >> 1;       // 4 warps over N (32 cols each)
    const int rowBase = blockIdx.x * BM;
    const int colBase = blockIdx.y * BN;

    // cp.async staging: each thread fills 2x16B of A and 2x16B of B per k-tile
    const int srow = tid >> 1;                 // 0..127
    const int scol = (tid & 1) * 8;            // 0 or 8 (floats)
    const int gr   = rowBase + srow;
    const uint32_t aok = (gr < M) ? 16u : 0u;
    const float* gaBase = A + (size_t)gr * RAW_K + scol;
    const float* gbBase = g_Wt + (size_t)wsel * DD * RAW_K
                        + (size_t)(colBase + srow) * RAW_K + scol;
    const uint32_t aSm = smem_u32(As) + (srow * PAD + scol) * 4;
    const uint32_t bSm = smem_u32(Bs) + (srow * PAD + scol) * 4;

    // ldmatrix fragment addressing
    const int lrow = lane & 15;
    const int lcol = (lane >> 4) << 2;         // 0 or 4
    const uint32_t aFrag = smem_u32(As) + ((warpM * 64 + lrow) * PAD + lcol) * 4;
    const uint32_t bFrag = smem_u32(Bs) + ((warpN * 32 + lrow) * PAD + lcol) * 4;

    float acc[4][4][4];
#pragma unroll
    for (int mt = 0; mt < 4; mt++)
#pragma unroll
        for (int nt = 0; nt < 4; nt++)
#pragma unroll
            for (int i = 0; i < 4; i++) acc[mt][nt][i] = 0.f;

#define ISSUE(kt, nb) do {                                                     \
        const int kb_ = (kt) * BK;                                             \
        const uint32_t da_ = aSm + (nb) * (TSTRIDE * 4);                       \
        const uint32_t db_ = bSm + (nb) * (TSTRIDE * 4);                       \
        cp16(da_,      gaBase + kb_,     aok);                                 \
        cp16(da_ + 16, gaBase + kb_ + 4, aok);                                 \
        cp16(db_,      gbBase + kb_,     16u);                                 \
        cp16(db_ + 16, gbBase + kb_ + 4, 16u);                                 \
    } while (0)

    ISSUE(0, 0); CP_COMMIT();

    const int nk = RAW_K / BK;   // 40
    for (int kt = 0; kt < nk; kt++) {
        const int buf = kt & 1;
        CP_WAIT0();
        __syncthreads();
        if (kt + 1 < nk) { ISSUE(kt + 1, buf ^ 1); CP_COMMIT(); }

        const uint32_t aB = aFrag + buf * (TSTRIDE * 4);
        const uint32_t bB = bFrag + buf * (TSTRIDE * 4);
#pragma unroll
        for (int s = 0; s < 2; s++) {
            const uint32_t ks = s * 32;        // 8 floats
            uint32_t af[4][4], bf[4][2];
#pragma unroll
            for (int mt = 0; mt < 4; mt++)
                LDSM4(af[mt][0], af[mt][1], af[mt][2], af[mt][3],
                      aB + mt * (16 * PAD * 4) + ks);
            LDSM4(bf[0][0], bf[1][0], bf[0][1], bf[1][1], bB + ks);
            LDSM4(bf[2][0], bf[3][0], bf[2][1], bf[3][1], bB + (16 * PAD * 4) + ks);
#pragma unroll
            for (int mt = 0; mt < 4; mt++)
#pragma unroll
                for (int nt = 0; nt < 4; nt++)
                    mma_tf32(acc[mt][nt], af[mt], bf[nt]);
        }
    }
#undef ISSUE

    // Epilogue: scatter-add of (acc + bias)/cnt -> g_agg (mean folded in)
#pragma unroll
    for (int mt = 0; mt < 4; mt++) {
        const int rA = rowBase + warpM * 64 + mt * 16 + g;
        const int rB = rA + 8;
        const bool okA = rA < M, okB = rB < M;
        const int nodeA = okA ? __ldg(&src[rA]) : 0;
        const int nodeB = okB ? __ldg(&src[rB]) : 0;
        const float invA = okA ? 1.f / fmaxf((float)__ldg(&g_counts[nodeA]), 1.f) : 0.f;
        const float invB = okB ? 1.f / fmaxf((float)__ldg(&g_counts[nodeB]), 1.f) : 0.f;
#pragma unroll
        for (int nt = 0; nt < 4; nt++) {
            const int c = colBase + warpN * 32 + nt * 8 + 2 * tg;
            const float b0v = __ldg(&bias[c]), b1v = __ldg(&bias[c + 1]);
            if (okA) red_add_v2(g_agg + (size_t)nodeA * DD + c,
                                (acc[mt][nt][0] + b0v) * invA,
                                (acc[mt][nt][1] + b1v) * invA);
            if (okB) red_add_v2(g_agg + (size_t)nodeB * DD + c,
                                (acc[mt][nt][2] + b0v) * invB,
                                (acc[mt][nt][3] + b1v) * invB);
        }
    }
}

// ---------------------------------------------------------------------------
// K4: gate GEMM [g_agg | memory](N x 512) @ g_Bt^T (j cols), cp.async +
//     ldmatrix, fully fused GRU epilogue -> out
// ---------------------------------------------------------------------------
__global__ __launch_bounds__(256)
void gru_gemm_tc(const float* __restrict__ mem, const float* __restrict__ bg,
                 float* __restrict__ out, int N)
{
    __shared__ __align__(16) float As[2][BM][PAD];
    __shared__ __align__(16) float Bs[2][BN][PAD];

    const int tid  = threadIdx.x;
    const int lane = tid & 31;
    const int warp = tid >> 5;
    const int g    = lane >> 2;
    const int tg   = lane & 3;
    const int warpM = warp & 1;
    const int warpN = warp >> 1;
    const int rowBase = blockIdx.x * BM;
    const int colBase = blockIdx.y * BN;   // packed-j block (grid.y = 8)

    const int srow = tid >> 1;
    const int scol = (tid & 1) * 8;
    const int gr   = rowBase + srow;
    const uint32_t aok = (gr < N) ? 16u : 0u;
    const float* gaAgg = g_agg + (size_t)gr * DD + scol;
    const float* gaMem = mem  + (size_t)gr * DD + scol;
    const float* gbBase = g_Bt + (size_t)(colBase + srow) * GKK + scol;
    const uint32_t aSm = smem_u32(As) + (srow * PAD + scol) * 4;
    const uint32_t bSm = smem_u32(Bs) + (srow * PAD + scol) * 4;

    const int lrow = lane & 15;
    const int lcol = (lane >> 4) << 2;
    const uint32_t aFrag = smem_u32(As) + ((warpM * 64 + lrow) * PAD + lcol) * 4;
    const uint32_t bFrag = smem_u32(Bs) + ((warpN * 32 + lrow) * PAD + lcol) * 4;

    float acc[4][4][4];
#pragma unroll
    for (int mt = 0; mt < 4; mt++)
#pragma unroll
        for (int nt = 0; nt < 4; nt++)
#pragma unroll
            for (int i = 0; i < 4; i++) acc[mt][nt][i] = 0.f;

#define ISSUE(kt, nb) do {                                                     \
        const int kb_ = (kt) * BK;                                             \
        const uint32_t da_ = aSm + (nb) * (TSTRIDE * 4);                       \
        const uint32_t db_ = bSm + (nb) * (TSTRIDE * 4);                       \
        const float* ga_ = (kb_ < 256) ? (gaAgg + kb_) : (gaMem + kb_ - 256);  \
        cp16(da_,      ga_,     aok);                                          \
        cp16(da_ + 16, ga_ + 4, aok);                                          \
        cp16(db_,      gbBase + kb_,     16u);                                 \
        cp16(db_ + 16, gbBase + kb_ + 4, 16u);                                 \
    } while (0)

    ISSUE(0, 0); CP_COMMIT();

    const int nk = GKK / BK;   // 32
    for (int kt = 0; kt < nk; kt++) {
        const int buf = kt & 1;
        CP_WAIT0();
        __syncthreads();
        if (kt + 1 < nk) { ISSUE(kt + 1, buf ^ 1); CP_COMMIT(); }

        const uint32_t aB = aFrag + buf * (TSTRIDE * 4);
        const uint32_t bB = bFrag + buf * (TSTRIDE * 4);
#pragma unroll
        for (int s = 0; s < 2; s++) {
            const uint32_t ks = s * 32;
            uint32_t af[4][4], bf[4][2];
#pragma unroll
            for (int mt = 0; mt < 4; mt++)
                LDSM4(af[mt][0], af[mt][1], af[mt][2], af[mt][3],
                      aB + mt * (16 * PAD * 4) + ks);
            LDSM4(bf[0][0], bf[1][0], bf[0][1], bf[1][1], bB + ks);
            LDSM4(bf[2][0], bf[3][0], bf[2][1], bf[3][1], bB + (16 * PAD * 4) + ks);
#pragma unroll
            for (int mt = 0; mt < 4; mt++)
#pragma unroll
                for (int nt = 0; nt < 4; nt++)
                    mma_tf32(acc[mt][nt], af[mt], bf[nt]);
        }
    }
#undef ISSUE

    // Fused GRU epilogue. Packed col c = 4*f + gate; even tg owns (r,z),
    // lane^1 partner owns (xn,hn); one shfl pairs them.
#pragma unroll
    for (int mt = 0; mt < 4; mt++) {
        const int rA = rowBase + warpM * 64 + mt * 16 + g;
        const int rB = rA + 8;
#pragma unroll
        for (int nt = 0; nt < 4; nt++) {
            float o0 = __shfl_xor_sync(0xffffffffu, acc[mt][nt][0], 1);
            float o1 = __shfl_xor_sync(0xffffffffu, acc[mt][nt][1], 1);
            float o2 = __shfl_xor_sync(0xffffffffu, acc[mt][nt][2], 1);
            float o3 = __shfl_xor_sync(0xffffffffu, acc[mt][nt][3], 1);
            if ((tg & 1) == 0) {
                const int c = colBase + warpN * 32 + nt * 8 + 2 * tg;
                const int f = c >> 2;
                const float br = __ldg(&bg[f]);
                const float bz = __ldg(&bg[256 + f]);
                const float bn = __ldg(&bg[512 + f]);
                if (rA < N) {
                    const float m = __ldg(&mem[(size_t)rA * DD + f]);
                    if (g_counts[rA] > 0) {
                        const float r = sigmoidf_(acc[mt][nt][0] + br);
                        const float z = sigmoidf_(acc[mt][nt][1] + bz);
                        const float n = tanhf(o0 + bn + r * o1);
                        out[(size_t)rA * DD + f] = (1.f - z) * n + z * m;
                    } else {
                        out[(size_t)rA * DD + f] = m;
                    }
                }
                if (rB < N) {
                    const float m = __ldg(&mem[(size_t)rB * DD + f]);
                    if (g_counts[rB] > 0) {
                        const float r = sigmoidf_(acc[mt][nt][2] + br);
                        const float z = sigmoidf_(acc[mt][nt][3] + bz);
                        const float n = tanhf(o2 + bn + r * o3);
                        out[(size_t)rB * DD + f] = (1.f - z) * n + z * m;
                    } else {
                        out[(size_t)rB * DD + f] = m;
                    }
                }
            }
        }
    }
}

// ---------------------------------------------------------------------------
// Launch
// ---------------------------------------------------------------------------
extern "C" void kernel_launch(void* const* d_in, const int* in_sizes, int n_in,
                              void* d_out, int out_size)
{
    const float* s_raw  = (const float*)d_in[0];
    const float* d_raw  = (const float*)d_in[1];
    const int*   s_src  = (const int*)  d_in[2];
    const int*   d_src  = (const int*)  d_in[3];
    // d_in[4], d_in[5] = s_t, d_t : dead in the reference output, skipped
    const float* W_src  = (const float*)d_in[6];
    const float* b_src  = (const float*)d_in[7];
    const float* W_dst  = (const float*)d_in[8];
    const float* b_dst  = (const float*)d_in[9];
    const float* W_gru  = (const float*)d_in[10];
    const float* U_gru  = (const float*)d_in[11];
    const float* b_gru  = (const float*)d_in[12];
    const float* memory = (const float*)d_in[13];

    const int M = in_sizes[2];            // 200000
    const int N = in_sizes[13] / DD;      // 100000
    float* out = (float*)d_out;
    const int n4 = N * (DD / 4);

    // K0: zero g_agg + counts
    zero_kernel<<<cdiv(n4, 256), 256>>>(n4, N);
    // K2: transpose + tf32-round weights
    pack_wt<<<cdiv(2 * DD * RAW_K, 256), 256>>>(W_src, W_dst);
    pack_bt<<<cdiv(JCOLS * GKK, 256), 256>>>(W_gru, U_gru);
    // K1: counts (must precede msg GEMMs — mean is folded into the scatter)
    count_kernel<<<cdiv(2 * M, 256), 256>>>(s_src, d_src, M);
    // K3: message GEMMs with fused mean-scatter into g_agg
    {
        dim3 grid(cdiv(M, BM), DD / BN);
        msg_gemm_tc<<<grid, 256>>>(s_raw, 0, b_src, s_src, M);
        msg_gemm_tc<<<grid, 256>>>(d_raw, 1, b_dst, d_src, M);
    }
    // K4: gate GEMM + fully fused GRU epilogue -> final new_memory in d_out
    {
        dim3 grid(cdiv(N, BM), JCOLS / BN);
        gru_gemm_tc<<<grid, 256>>>(memory, b_gru, out, N);
    }
}